// round 8
// baseline (speedup 1.0000x reference)
#include <cuda_runtime.h>

#define BN      32768      // total nodes
#define NE      1048576    // total edges
#define NPG     512        // nodes per graph
#define EPG     16384      // edges per graph
#define KKEEP   256        // topk keep
#define NGRAPH  64
#define EPSM    1e-7f

// ---------------- scratch (device globals; no allocation allowed) ----------
__device__ float g_h   [BN * 16];
__device__ float g_h1  [BN * 16];
__device__ float g_hp  [BN * 16];
__device__ float g_h2  [BN * 32];
__device__ float g_mask[BN];
__device__ int   g_off[BN + 1];
__device__ int2  g_se  [NE];         // (src, eid) pairs, CSR(dst)-ordered

// ---------------- warp helpers ----------------
__device__ __forceinline__ float wsum(float v) {
    #pragma unroll
    for (int o = 16; o > 0; o >>= 1) v += __shfl_xor_sync(0xffffffffu, v, o);
    return v;
}

// ---------------- CSR build: hist + scan + scatter, one block per graph ---
__global__ __launch_bounds__(512)
void build_csr_kernel(const int* __restrict__ ei) {
    __shared__ int sh[NPG];      // histogram, then cursor
    __shared__ int wsums[16];
    int g = blockIdx.x, tid = threadIdx.x, lane = tid & 31, w = tid >> 5;
    sh[tid] = 0;
    __syncthreads();
    int base = g * EPG;
    #pragma unroll 4
    for (int it = 0; it < EPG / 512; it++) {
        int e = base + it * 512 + tid;
        int d = ei[NE + e] - g * NPG;
        if ((unsigned)d < NPG) atomicAdd(&sh[d], 1);
    }
    __syncthreads();
    // exclusive scan of sh[0..511]
    int v = sh[tid];
    int x = v;
    #pragma unroll
    for (int o = 1; o < 32; o <<= 1) {
        int y = __shfl_up_sync(0xffffffffu, x, o);
        if (lane >= o) x += y;
    }
    if (lane == 31) wsums[w] = x;
    __syncthreads();
    if (w == 0) {
        int s = (lane < 16) ? wsums[lane] : 0;
        #pragma unroll
        for (int o = 1; o < 16; o <<= 1) {
            int y = __shfl_up_sync(0xffffffffu, s, o);
            if (lane >= o) s += y;
        }
        if (lane < 16) wsums[lane] = s;
    }
    __syncthreads();
    int woff = (w == 0) ? 0 : wsums[w - 1];
    int incl = woff + x;
    int node = g * NPG + tid;
    g_off[node + 1] = base + incl;
    if (g == 0 && tid == 0) g_off[0] = 0;
    __syncthreads();
    sh[tid] = incl - v;          // local exclusive offset -> cursor
    __syncthreads();
    // scatter pass
    #pragma unroll 4
    for (int it = 0; it < EPG / 512; it++) {
        int e = base + it * 512 + tid;
        int d = ei[NE + e] - g * NPG;
        int s = ei[e];
        if ((unsigned)s >= BN) s = 0;
        if ((unsigned)d < NPG) {
            int p = atomicAdd(&sh[d], 1);
            if ((unsigned)p < EPG) g_se[base + p] = make_int2(s, e);
        }
    }
}

// ---------------- node encode: h = x @ W_ne + b_ne ----------------
__global__ void encode_kernel(const float* __restrict__ x,
                              const float* __restrict__ Wne,
                              const float* __restrict__ bne) {
    __shared__ float sW[64 * 16];
    __shared__ float sb[16];
    int tx = threadIdx.x;
    for (int i = tx; i < 64 * 16; i += blockDim.x) sW[i] = Wne[i];
    if (tx < 16) sb[tx] = bne[tx];
    __syncthreads();
    int node = blockIdx.x * blockDim.x + tx;
    if (node >= BN) return;
    float acc[16];
    #pragma unroll
    for (int f = 0; f < 16; f++) acc[f] = sb[f];
    const float4* xp = (const float4*)(x + (size_t)node * 64);
    #pragma unroll
    for (int j4 = 0; j4 < 16; j4++) {
        float4 v = __ldg(xp + j4);
        float vv[4] = {v.x, v.y, v.z, v.w};
        #pragma unroll
        for (int k = 0; k < 4; k++) {
            int j = j4 * 4 + k;
            #pragma unroll
            for (int f = 0; f < 16; f++) acc[f] += vv[k] * sW[j * 16 + f];
        }
    }
    float4* op = (float4*)(g_h + (size_t)node * 16);
    op[0] = make_float4(acc[0], acc[1], acc[2], acc[3]);
    op[1] = make_float4(acc[4], acc[5], acc[6], acc[7]);
    op[2] = make_float4(acc[8], acc[9], acc[10], acc[11]);
    op[3] = make_float4(acc[12], acc[13], acc[14], acc[15]);
}

// ---------------- GENConv layer 1 (16 -> 32 -> 16) ----------------
__global__ __launch_bounds__(256)
void conv1_kernel(const int* __restrict__ eidx,
                  const float* __restrict__ eattr,
                  const float* __restrict__ Wee, const float* __restrict__ bee,
                  const float* __restrict__ tptr,
                  const float* __restrict__ W1a, const float* __restrict__ b1a,
                  const float* __restrict__ g1,  const float* __restrict__ be1,
                  const float* __restrict__ W1b, const float* __restrict__ b1b) {
    __shared__ float sWee[256], sbee[16];
    __shared__ float sW1a[512], sb1a[32], sg1[32], sbe1[32];
    __shared__ float sW1b[512], sb1b[16];
    __shared__ float sh_hid[8][33];
    int tx = threadIdx.x;
    for (int i = tx; i < 512; i += 256) { sW1a[i] = W1a[i]; sW1b[i] = W1b[i]; }
    if (tx < 256) sWee[tx] = Wee[tx];
    if (tx < 32) { sb1a[tx] = b1a[tx]; sg1[tx] = g1[tx]; sbe1[tx] = be1[tx]; }
    if (tx < 16) { sbee[tx] = bee[tx]; sb1b[tx] = b1b[tx]; }
    __syncthreads();

    int w = tx >> 5, lane = tx & 31;
    int node = blockIdx.x * 8 + w;
    int start = g_off[node], end = g_off[node + 1];
    if (start < 0) start = 0;
    if (end > NE) end = NE;
    float t = __ldg(tptr);

    float den[16], num[16];
    #pragma unroll
    for (int f = 0; f < 16; f++) { den[f] = 0.f; num[f] = 0.f; }

    for (int e0 = start; e0 < end; e0 += 32) {
        int idx = e0 + lane;
        if (idx < end) {
            int2 se = g_se[idx];
            int src = se.x, eid = se.y;
            float at[16];
            const float4* ap = (const float4*)(eattr) + (size_t)eid * 4;
            float4 v;
            v = __ldg(ap + 0); at[0]  = v.x; at[1]  = v.y; at[2]  = v.z; at[3]  = v.w;
            v = __ldg(ap + 1); at[4]  = v.x; at[5]  = v.y; at[6]  = v.z; at[7]  = v.w;
            v = __ldg(ap + 2); at[8]  = v.x; at[9]  = v.y; at[10] = v.z; at[11] = v.w;
            v = __ldg(ap + 3); at[12] = v.x; at[13] = v.y; at[14] = v.z; at[15] = v.w;
            float hs[16];
            const float4* hp4 = (const float4*)(g_h) + (size_t)src * 4;
            v = hp4[0]; hs[0]  = v.x; hs[1]  = v.y; hs[2]  = v.z; hs[3]  = v.w;
            v = hp4[1]; hs[4]  = v.x; hs[5]  = v.y; hs[6]  = v.z; hs[7]  = v.w;
            v = hp4[2]; hs[8]  = v.x; hs[9]  = v.y; hs[10] = v.z; hs[11] = v.w;
            v = hp4[3]; hs[12] = v.x; hs[13] = v.y; hs[14] = v.z; hs[15] = v.w;
            #pragma unroll
            for (int f = 0; f < 16; f++) {
                float acc = sbee[f];
                #pragma unroll
                for (int j = 0; j < 16; j++) acc += at[j] * sWee[j * 16 + f];
                float msg = fmaxf(hs[f] + acc, 0.f) + EPSM;
                float ev = __expf(t * msg);
                den[f] += ev;
                num[f] += ev * msg;
            }
        }
    }

    float pre[16];
    #pragma unroll
    for (int f = 0; f < 16; f++) {
        float dsum = wsum(den[f]);
        float nsum = wsum(num[f]);
        pre[f] = g_h[(size_t)node * 16 + f] + nsum / fmaxf(dsum, 1e-16f);
    }

    // MLP: 16 -> 32 (LN, relu) -> 16 (then outer relu)
    float acc = sb1a[lane];
    #pragma unroll
    for (int f = 0; f < 16; f++) acc += pre[f] * sW1a[f * 32 + lane];
    float mu = wsum(acc) * (1.f / 32.f);
    float d = acc - mu;
    float var = wsum(d * d) * (1.f / 32.f);
    float y = d * rsqrtf(var + 1e-5f) * sg1[lane] + sbe1[lane];
    y = fmaxf(y, 0.f);
    sh_hid[w][lane] = y;
    __syncwarp();
    if (lane < 16) {
        float o = sb1b[lane];
        #pragma unroll
        for (int l = 0; l < 32; l++) o += sh_hid[w][l] * sW1b[l * 16 + lane];
        g_h1[(size_t)node * 16 + lane] = fmaxf(o, 0.f);
    }
}

// ---------------- TopK pooling (score + mask + hp) ----------------
__global__ void topk_kernel(const float* __restrict__ wpool) {
    __shared__ float s[512];
    __shared__ float swp[16];
    int tid = threadIdx.x;
    if (tid < 16) swp[tid] = wpool[tid];
    __syncthreads();
    float nrm2 = 0.f;
    #pragma unroll
    for (int j = 0; j < 16; j++) nrm2 += swp[j] * swp[j];
    float inv = rsqrtf(nrm2);
    int node = blockIdx.x * NPG + tid;
    const float4* hp4 = (const float4*)(g_h1) + (size_t)node * 4;
    float4 r0 = hp4[0], r1 = hp4[1], r2 = hp4[2], r3 = hp4[3];
    float dot = r0.x * swp[0] + r0.y * swp[1] + r0.z * swp[2] + r0.w * swp[3]
              + r1.x * swp[4] + r1.y * swp[5] + r1.z * swp[6] + r1.w * swp[7]
              + r2.x * swp[8] + r2.y * swp[9] + r2.z * swp[10] + r2.w * swp[11]
              + r3.x * swp[12] + r3.y * swp[13] + r3.z * swp[14] + r3.w * swp[15];
    float sc = dot * inv;
    s[tid] = sc;
    __syncthreads();
    int rank = 0;
    for (int j = 0; j < NPG; j++) {
        float sj = s[j];
        rank += (sj > sc) || (sj == sc && j < tid);
    }
    int kept = rank < KKEEP;
    g_mask[node] = kept ? 1.f : 0.f;
    float fac = kept ? tanhf(sc) : 0.f;
    float4* op = (float4*)(g_hp) + (size_t)node * 4;
    op[0] = make_float4(r0.x * fac, r0.y * fac, r0.z * fac, r0.w * fac);
    op[1] = make_float4(r1.x * fac, r1.y * fac, r1.z * fac, r1.w * fac);
    op[2] = make_float4(r2.x * fac, r2.y * fac, r2.z * fac, r2.w * fac);
    op[3] = make_float4(r3.x * fac, r3.y * fac, r3.z * fac, r3.w * fac);
}

// ---------------- GENConv layer 2 (16 -> 32 -> 32), kept nodes only -------
__global__ __launch_bounds__(256)
void conv2_kernel(const float* __restrict__ eattr,
                  const float* __restrict__ Wee, const float* __restrict__ bee,
                  const float* __restrict__ tptr,
                  const float* __restrict__ W2a, const float* __restrict__ b2a,
                  const float* __restrict__ g2,  const float* __restrict__ be2,
                  const float* __restrict__ W2b, const float* __restrict__ b2b) {
    __shared__ float sWee[256], sbee[16];
    __shared__ float sW2a[512], sb2a[32], sg2[32], sbe2[32];
    __shared__ float sW2b[1024], sb2b[32];
    __shared__ float sh_hid[8][33];
    int tx = threadIdx.x;
    for (int i = tx; i < 1024; i += 256) sW2b[i] = W2b[i];
    for (int i = tx; i < 512; i += 256) sW2a[i] = W2a[i];
    if (tx < 256) sWee[tx] = Wee[tx];
    if (tx < 32) { sb2a[tx] = b2a[tx]; sg2[tx] = g2[tx]; sbe2[tx] = be2[tx]; sb2b[tx] = b2b[tx]; }
    if (tx < 16) sbee[tx] = bee[tx];
    __syncthreads();

    int w = tx >> 5, lane = tx & 31;
    int node = blockIdx.x * 8 + w;
    if (g_mask[node] == 0.f) return;   // not kept: h2 never read
    int start = g_off[node], end = g_off[node + 1];
    if (start < 0) start = 0;
    if (end > NE) end = NE;
    float t = __ldg(tptr);

    float den[16], num[16];
    #pragma unroll
    for (int f = 0; f < 16; f++) { den[f] = 0.f; num[f] = 0.f; }

    for (int e0 = start; e0 < end; e0 += 32) {
        int idx = e0 + lane;
        if (idx < end) {
            int2 se = g_se[idx];
            int src = se.x, eid = se.y;
            if (g_mask[src] != 0.f) {
                float at[16];
                const float4* ap = (const float4*)(eattr) + (size_t)eid * 4;
                float4 v;
                v = __ldg(ap + 0); at[0]  = v.x; at[1]  = v.y; at[2]  = v.z; at[3]  = v.w;
                v = __ldg(ap + 1); at[4]  = v.x; at[5]  = v.y; at[6]  = v.z; at[7]  = v.w;
                v = __ldg(ap + 2); at[8]  = v.x; at[9]  = v.y; at[10] = v.z; at[11] = v.w;
                v = __ldg(ap + 3); at[12] = v.x; at[13] = v.y; at[14] = v.z; at[15] = v.w;
                float hs[16];
                const float4* hp4 = (const float4*)(g_hp) + (size_t)src * 4;
                v = hp4[0]; hs[0]  = v.x; hs[1]  = v.y; hs[2]  = v.z; hs[3]  = v.w;
                v = hp4[1]; hs[4]  = v.x; hs[5]  = v.y; hs[6]  = v.z; hs[7]  = v.w;
                v = hp4[2]; hs[8]  = v.x; hs[9]  = v.y; hs[10] = v.z; hs[11] = v.w;
                v = hp4[3]; hs[12] = v.x; hs[13] = v.y; hs[14] = v.z; hs[15] = v.w;
                #pragma unroll
                for (int f = 0; f < 16; f++) {
                    float acc = sbee[f];
                    #pragma unroll
                    for (int j = 0; j < 16; j++) acc += at[j] * sWee[j * 16 + f];
                    float msg = fmaxf(hs[f] + acc, 0.f) + EPSM;
                    float ev = __expf(t * msg);
                    den[f] += ev;
                    num[f] += ev * msg;
                }
            }
        }
    }

    float pre[16];
    #pragma unroll
    for (int f = 0; f < 16; f++) {
        float dsum = wsum(den[f]);
        float nsum = wsum(num[f]);
        pre[f] = g_hp[(size_t)node * 16 + f] + nsum / fmaxf(dsum, 1e-16f);
    }

    // MLP: 16 -> 32 (LN, relu) -> 32 (then outer relu)
    float acc = sb2a[lane];
    #pragma unroll
    for (int f = 0; f < 16; f++) acc += pre[f] * sW2a[f * 32 + lane];
    float mu = wsum(acc) * (1.f / 32.f);
    float d = acc - mu;
    float var = wsum(d * d) * (1.f / 32.f);
    float y = d * rsqrtf(var + 1e-5f) * sg2[lane] + sbe2[lane];
    y = fmaxf(y, 0.f);
    sh_hid[w][lane] = y;
    __syncwarp();
    float o = sb2b[lane];
    #pragma unroll
    for (int k = 0; k < 32; k++) o += sh_hid[w][k] * sW2b[k * 32 + lane];
    g_h2[(size_t)node * 32 + lane] = fmaxf(o, 0.f);
}

// ---------------- pool + head: out = tanh(relu(pooled@Wa+ba)@Wo+bo) -------
__global__ void final_kernel(const float* __restrict__ Wa, const float* __restrict__ ba,
                             const float* __restrict__ Wo, const float* __restrict__ bo,
                             float* __restrict__ out) {
    __shared__ float part[128];
    __shared__ float pooled[32];
    __shared__ float sa[128];
    int t = threadIdx.x;
    int g = blockIdx.x;
    int c = t & 31, grp = t >> 5;
    float acc = 0.f;
    for (int n = grp; n < NPG; n += 4) {
        int node = g * NPG + n;
        if (g_mask[node] != 0.f) acc += g_h2[(size_t)node * 32 + c];
    }
    part[t] = acc;
    __syncthreads();
    if (t < 32) pooled[t] = (part[t] + part[t + 32] + part[t + 64] + part[t + 96]) * (1.f / KKEEP);
    __syncthreads();
    float a = ba[t];
    #pragma unroll
    for (int cc = 0; cc < 32; cc++) a += pooled[cc] * Wa[cc * 128 + t];
    sa[t] = fmaxf(a, 0.f);
    __syncthreads();
    if (t < 4) {
        float o = bo[t];
        for (int k = 0; k < 128; k++) o += sa[k] * Wo[k * 4 + t];
        out[g * 4 + t] = tanhf(o);
    }
}

// ---------------- launch ----------------
extern "C" void kernel_launch(void* const* d_in, const int* in_sizes, int n_in,
                              void* d_out, int out_size) {
    const float* x    = (const float*)d_in[0];
    const int*   ei   = (const int*)d_in[1];
    const float* ea   = (const float*)d_in[2];
    const float* Wne  = (const float*)d_in[3];
    const float* bne  = (const float*)d_in[4];
    const float* Wee  = (const float*)d_in[5];
    const float* bee  = (const float*)d_in[6];
    const float* t1   = (const float*)d_in[7];
    const float* W1a  = (const float*)d_in[8];
    const float* b1a  = (const float*)d_in[9];
    const float* g1   = (const float*)d_in[10];
    const float* be1  = (const float*)d_in[11];
    const float* W1b  = (const float*)d_in[12];
    const float* b1b  = (const float*)d_in[13];
    const float* wpl  = (const float*)d_in[14];
    const float* t2   = (const float*)d_in[15];
    const float* W2a  = (const float*)d_in[16];
    const float* b2a  = (const float*)d_in[17];
    const float* g2   = (const float*)d_in[18];
    const float* be2  = (const float*)d_in[19];
    const float* W2b  = (const float*)d_in[20];
    const float* b2b  = (const float*)d_in[21];
    const float* Wa   = (const float*)d_in[22];
    const float* ba   = (const float*)d_in[23];
    const float* Wo   = (const float*)d_in[24];
    const float* bo   = (const float*)d_in[25];
    float* out = (float*)d_out;

    build_csr_kernel<<<NGRAPH, 512>>>(ei);
    encode_kernel<<<BN / 256, 256>>>(x, Wne, bne);
    conv1_kernel<<<BN / 8, 256>>>(ei, ea, Wee, bee, t1,
                                  W1a, b1a, g1, be1, W1b, b1b);
    topk_kernel<<<NGRAPH, NPG>>>(wpl);
    conv2_kernel<<<BN / 8, 256>>>(ea, Wee, bee, t2,
                                  W2a, b2a, g2, be2, W2b, b2b);
    final_kernel<<<NGRAPH, 128>>>(Wa, ba, Wo, bo, out);
}

// round 9
// speedup vs baseline: 1.7249x; 1.7249x over previous
#include <cuda_runtime.h>

#define BN      32768      // total nodes
#define NE      1048576    // total edges
#define NPG     512        // nodes per graph
#define EPG     16384      // edges per graph
#define KKEEP   256        // topk keep
#define NGRAPH  64
#define EPSM    1e-7f

// ---------------- scratch (device globals; no allocation allowed) ----------
__device__ float g_h   [BN * 16];
__device__ float g_h1  [BN * 16];
__device__ float g_hp  [BN * 16];
__device__ float g_h2  [BN * 32];
__device__ float g_mask[BN];
__device__ int   g_off[BN + 1];
__device__ int2  g_se  [NE];         // (src, eid) pairs, CSR(dst)-ordered
__device__ float g_ea  [NE * 16];    // encoded edge attr, ORIGINAL edge order

// ---------------- warp helpers ----------------
__device__ __forceinline__ float wsum(float v) {
    #pragma unroll
    for (int o = 16; o > 0; o >>= 1) v += __shfl_xor_sync(0xffffffffu, v, o);
    return v;
}

// ---------------- edge encode (original order, fully coalesced) -----------
__global__ __launch_bounds__(256)
void encode_edges_kernel(const float* __restrict__ eattr,
                         const float* __restrict__ Wee,
                         const float* __restrict__ bee) {
    __shared__ float sW[256], sb[16];
    int tx = threadIdx.x;
    if (tx < 256) sW[tx] = Wee[tx];
    if (tx < 16) sb[tx] = bee[tx];
    __syncthreads();
    int e = blockIdx.x * blockDim.x + tx;
    if (e >= NE) return;

    float at[16];
    const float4* ap = (const float4*)(eattr) + (size_t)e * 4;
    float4 v;
    v = __ldg(ap + 0); at[0] = v.x; at[1] = v.y; at[2]  = v.z; at[3]  = v.w;
    v = __ldg(ap + 1); at[4] = v.x; at[5] = v.y; at[6]  = v.z; at[7]  = v.w;
    v = __ldg(ap + 2); at[8] = v.x; at[9] = v.y; at[10] = v.z; at[11] = v.w;
    v = __ldg(ap + 3); at[12] = v.x; at[13] = v.y; at[14] = v.z; at[15] = v.w;

    float enc[16];
    #pragma unroll
    for (int f = 0; f < 16; f++) {
        float acc = sb[f];
        #pragma unroll
        for (int j = 0; j < 16; j++) acc += at[j] * sW[j * 16 + f];
        enc[f] = acc;
    }
    float4* op = (float4*)(g_ea) + (size_t)e * 4;
    op[0] = make_float4(enc[0],  enc[1],  enc[2],  enc[3]);
    op[1] = make_float4(enc[4],  enc[5],  enc[6],  enc[7]);
    op[2] = make_float4(enc[8],  enc[9],  enc[10], enc[11]);
    op[3] = make_float4(enc[12], enc[13], enc[14], enc[15]);
}

// ---------------- CSR build: hist + scan + scatter, one block per graph ---
__global__ __launch_bounds__(512)
void build_csr_kernel(const int* __restrict__ ei) {
    __shared__ int sh[NPG];      // histogram, then cursor
    __shared__ int wsums[16];
    int g = blockIdx.x, tid = threadIdx.x, lane = tid & 31, w = tid >> 5;
    sh[tid] = 0;
    __syncthreads();
    int base = g * EPG;
    #pragma unroll 4
    for (int it = 0; it < EPG / 512; it++) {
        int e = base + it * 512 + tid;
        int d = ei[NE + e] - g * NPG;
        if ((unsigned)d < NPG) atomicAdd(&sh[d], 1);
    }
    __syncthreads();
    // exclusive scan of sh[0..511]
    int v = sh[tid];
    int x = v;
    #pragma unroll
    for (int o = 1; o < 32; o <<= 1) {
        int y = __shfl_up_sync(0xffffffffu, x, o);
        if (lane >= o) x += y;
    }
    if (lane == 31) wsums[w] = x;
    __syncthreads();
    if (w == 0) {
        int s = (lane < 16) ? wsums[lane] : 0;
        #pragma unroll
        for (int o = 1; o < 16; o <<= 1) {
            int y = __shfl_up_sync(0xffffffffu, s, o);
            if (lane >= o) s += y;
        }
        if (lane < 16) wsums[lane] = s;
    }
    __syncthreads();
    int woff = (w == 0) ? 0 : wsums[w - 1];
    int incl = woff + x;
    int node = g * NPG + tid;
    g_off[node + 1] = base + incl;
    if (g == 0 && tid == 0) g_off[0] = 0;
    __syncthreads();
    sh[tid] = incl - v;          // local exclusive offset -> cursor
    __syncthreads();
    // scatter pass
    #pragma unroll 4
    for (int it = 0; it < EPG / 512; it++) {
        int e = base + it * 512 + tid;
        int d = ei[NE + e] - g * NPG;
        int s = ei[e];
        if ((unsigned)s >= BN) s = 0;
        if ((unsigned)d < NPG) {
            int p = atomicAdd(&sh[d], 1);
            if ((unsigned)p < EPG) g_se[base + p] = make_int2(s, e);
        }
    }
}

// ---------------- node encode: h = x @ W_ne + b_ne ----------------
__global__ void encode_kernel(const float* __restrict__ x,
                              const float* __restrict__ Wne,
                              const float* __restrict__ bne) {
    __shared__ float sW[64 * 16];
    __shared__ float sb[16];
    int tx = threadIdx.x;
    for (int i = tx; i < 64 * 16; i += blockDim.x) sW[i] = Wne[i];
    if (tx < 16) sb[tx] = bne[tx];
    __syncthreads();
    int node = blockIdx.x * blockDim.x + tx;
    if (node >= BN) return;
    float acc[16];
    #pragma unroll
    for (int f = 0; f < 16; f++) acc[f] = sb[f];
    const float4* xp = (const float4*)(x + (size_t)node * 64);
    #pragma unroll
    for (int j4 = 0; j4 < 16; j4++) {
        float4 v = __ldg(xp + j4);
        float vv[4] = {v.x, v.y, v.z, v.w};
        #pragma unroll
        for (int k = 0; k < 4; k++) {
            int j = j4 * 4 + k;
            #pragma unroll
            for (int f = 0; f < 16; f++) acc[f] += vv[k] * sW[j * 16 + f];
        }
    }
    float4* op = (float4*)(g_h + (size_t)node * 16);
    op[0] = make_float4(acc[0], acc[1], acc[2], acc[3]);
    op[1] = make_float4(acc[4], acc[5], acc[6], acc[7]);
    op[2] = make_float4(acc[8], acc[9], acc[10], acc[11]);
    op[3] = make_float4(acc[12], acc[13], acc[14], acc[15]);
}

// ---------------- GENConv layer 1 (16 -> 32 -> 16) ----------------
__global__ __launch_bounds__(256)
void conv1_kernel(const float* __restrict__ tptr,
                  const float* __restrict__ W1a, const float* __restrict__ b1a,
                  const float* __restrict__ g1,  const float* __restrict__ be1,
                  const float* __restrict__ W1b, const float* __restrict__ b1b) {
    __shared__ float sW1a[512], sb1a[32], sg1[32], sbe1[32];
    __shared__ float sW1b[512], sb1b[16];
    __shared__ float sh_hid[8][33];
    int tx = threadIdx.x;
    for (int i = tx; i < 512; i += 256) { sW1a[i] = W1a[i]; sW1b[i] = W1b[i]; }
    if (tx < 32) { sb1a[tx] = b1a[tx]; sg1[tx] = g1[tx]; sbe1[tx] = be1[tx]; }
    if (tx < 16) { sb1b[tx] = b1b[tx]; }
    __syncthreads();

    int w = tx >> 5, lane = tx & 31;
    int node = blockIdx.x * 8 + w;
    int start = g_off[node], end = g_off[node + 1];
    if (start < 0) start = 0;
    if (end > NE) end = NE;
    float t = __ldg(tptr);

    float den[16], num[16];
    #pragma unroll
    for (int f = 0; f < 16; f++) { den[f] = 0.f; num[f] = 0.f; }

    for (int e0 = start; e0 < end; e0 += 32) {
        int idx = e0 + lane;
        if (idx < end) {
            int2 se = g_se[idx];
            int src = se.x, eid = se.y;
            const float4* ep  = (const float4*)(g_ea) + (size_t)eid * 4;
            const float4* hp4 = (const float4*)(g_h)  + (size_t)src * 4;
            float4 e0v = ep[0], e1v = ep[1], e2v = ep[2], e3v = ep[3];
            float4 h0 = hp4[0], h1 = hp4[1], h2 = hp4[2], h3 = hp4[3];
            float msg[16];
            msg[0]  = fmaxf(h0.x + e0v.x, 0.f) + EPSM;
            msg[1]  = fmaxf(h0.y + e0v.y, 0.f) + EPSM;
            msg[2]  = fmaxf(h0.z + e0v.z, 0.f) + EPSM;
            msg[3]  = fmaxf(h0.w + e0v.w, 0.f) + EPSM;
            msg[4]  = fmaxf(h1.x + e1v.x, 0.f) + EPSM;
            msg[5]  = fmaxf(h1.y + e1v.y, 0.f) + EPSM;
            msg[6]  = fmaxf(h1.z + e1v.z, 0.f) + EPSM;
            msg[7]  = fmaxf(h1.w + e1v.w, 0.f) + EPSM;
            msg[8]  = fmaxf(h2.x + e2v.x, 0.f) + EPSM;
            msg[9]  = fmaxf(h2.y + e2v.y, 0.f) + EPSM;
            msg[10] = fmaxf(h2.z + e2v.z, 0.f) + EPSM;
            msg[11] = fmaxf(h2.w + e2v.w, 0.f) + EPSM;
            msg[12] = fmaxf(h3.x + e3v.x, 0.f) + EPSM;
            msg[13] = fmaxf(h3.y + e3v.y, 0.f) + EPSM;
            msg[14] = fmaxf(h3.z + e3v.z, 0.f) + EPSM;
            msg[15] = fmaxf(h3.w + e3v.w, 0.f) + EPSM;
            #pragma unroll
            for (int f = 0; f < 16; f++) {
                float ev = __expf(t * msg[f]);
                den[f] += ev;
                num[f] += ev * msg[f];
            }
        }
    }

    float pre[16];
    #pragma unroll
    for (int f = 0; f < 16; f++) {
        float dsum = wsum(den[f]);
        float nsum = wsum(num[f]);
        pre[f] = g_h[(size_t)node * 16 + f] + nsum / fmaxf(dsum, 1e-16f);
    }

    // MLP: 16 -> 32 (LN, relu) -> 16 (then outer relu)
    float acc = sb1a[lane];
    #pragma unroll
    for (int f = 0; f < 16; f++) acc += pre[f] * sW1a[f * 32 + lane];
    float mu = wsum(acc) * (1.f / 32.f);
    float d = acc - mu;
    float var = wsum(d * d) * (1.f / 32.f);
    float y = d * rsqrtf(var + 1e-5f) * sg1[lane] + sbe1[lane];
    y = fmaxf(y, 0.f);
    sh_hid[w][lane] = y;
    __syncwarp();
    if (lane < 16) {
        float o = sb1b[lane];
        #pragma unroll
        for (int l = 0; l < 32; l++) o += sh_hid[w][l] * sW1b[l * 16 + lane];
        g_h1[(size_t)node * 16 + lane] = fmaxf(o, 0.f);
    }
}

// ---------------- TopK pooling (score + mask + hp) ----------------
__global__ void topk_kernel(const float* __restrict__ wpool) {
    __shared__ float s[512];
    __shared__ float swp[16];
    int tid = threadIdx.x;
    if (tid < 16) swp[tid] = wpool[tid];
    __syncthreads();
    float nrm2 = 0.f;
    #pragma unroll
    for (int j = 0; j < 16; j++) nrm2 += swp[j] * swp[j];
    float inv = rsqrtf(nrm2);
    int node = blockIdx.x * NPG + tid;
    const float4* hp4 = (const float4*)(g_h1) + (size_t)node * 4;
    float4 r0 = hp4[0], r1 = hp4[1], r2 = hp4[2], r3 = hp4[3];
    float dot = r0.x * swp[0] + r0.y * swp[1] + r0.z * swp[2] + r0.w * swp[3]
              + r1.x * swp[4] + r1.y * swp[5] + r1.z * swp[6] + r1.w * swp[7]
              + r2.x * swp[8] + r2.y * swp[9] + r2.z * swp[10] + r2.w * swp[11]
              + r3.x * swp[12] + r3.y * swp[13] + r3.z * swp[14] + r3.w * swp[15];
    float sc = dot * inv;
    s[tid] = sc;
    __syncthreads();
    int rank = 0;
    for (int j = 0; j < NPG; j++) {
        float sj = s[j];
        rank += (sj > sc) || (sj == sc && j < tid);
    }
    int kept = rank < KKEEP;
    g_mask[node] = kept ? 1.f : 0.f;
    float fac = kept ? tanhf(sc) : 0.f;
    float4* op = (float4*)(g_hp) + (size_t)node * 4;
    op[0] = make_float4(r0.x * fac, r0.y * fac, r0.z * fac, r0.w * fac);
    op[1] = make_float4(r1.x * fac, r1.y * fac, r1.z * fac, r1.w * fac);
    op[2] = make_float4(r2.x * fac, r2.y * fac, r2.z * fac, r2.w * fac);
    op[3] = make_float4(r3.x * fac, r3.y * fac, r3.z * fac, r3.w * fac);
}

// ---------------- GENConv layer 2 (16 -> 32 -> 32), kept nodes only -------
__global__ __launch_bounds__(256)
void conv2_kernel(const float* __restrict__ tptr,
                  const float* __restrict__ W2a, const float* __restrict__ b2a,
                  const float* __restrict__ g2,  const float* __restrict__ be2,
                  const float* __restrict__ W2b, const float* __restrict__ b2b) {
    __shared__ float sW2a[512], sb2a[32], sg2[32], sbe2[32];
    __shared__ float sW2b[1024], sb2b[32];
    __shared__ float sh_hid[8][33];
    int tx = threadIdx.x;
    for (int i = tx; i < 1024; i += 256) sW2b[i] = W2b[i];
    for (int i = tx; i < 512; i += 256) sW2a[i] = W2a[i];
    if (tx < 32) { sb2a[tx] = b2a[tx]; sg2[tx] = g2[tx]; sbe2[tx] = be2[tx]; sb2b[tx] = b2b[tx]; }
    __syncthreads();

    int w = tx >> 5, lane = tx & 31;
    int node = blockIdx.x * 8 + w;
    if (g_mask[node] == 0.f) return;   // not kept: h2 never read
    int start = g_off[node], end = g_off[node + 1];
    if (start < 0) start = 0;
    if (end > NE) end = NE;
    float t = __ldg(tptr);

    float den[16], num[16];
    #pragma unroll
    for (int f = 0; f < 16; f++) { den[f] = 0.f; num[f] = 0.f; }

    for (int e0 = start; e0 < end; e0 += 32) {
        int idx = e0 + lane;
        if (idx < end) {
            int2 se = g_se[idx];
            int src = se.x, eid = se.y;
            if (g_mask[src] != 0.f) {
                const float4* ep  = (const float4*)(g_ea) + (size_t)eid * 4;
                const float4* hp4 = (const float4*)(g_hp) + (size_t)src * 4;
                float4 e0v = ep[0], e1v = ep[1], e2v = ep[2], e3v = ep[3];
                float4 h0 = hp4[0], h1 = hp4[1], h2 = hp4[2], h3 = hp4[3];
                float msg[16];
                msg[0]  = fmaxf(h0.x + e0v.x, 0.f) + EPSM;
                msg[1]  = fmaxf(h0.y + e0v.y, 0.f) + EPSM;
                msg[2]  = fmaxf(h0.z + e0v.z, 0.f) + EPSM;
                msg[3]  = fmaxf(h0.w + e0v.w, 0.f) + EPSM;
                msg[4]  = fmaxf(h1.x + e1v.x, 0.f) + EPSM;
                msg[5]  = fmaxf(h1.y + e1v.y, 0.f) + EPSM;
                msg[6]  = fmaxf(h1.z + e1v.z, 0.f) + EPSM;
                msg[7]  = fmaxf(h1.w + e1v.w, 0.f) + EPSM;
                msg[8]  = fmaxf(h2.x + e2v.x, 0.f) + EPSM;
                msg[9]  = fmaxf(h2.y + e2v.y, 0.f) + EPSM;
                msg[10] = fmaxf(h2.z + e2v.z, 0.f) + EPSM;
                msg[11] = fmaxf(h2.w + e2v.w, 0.f) + EPSM;
                msg[12] = fmaxf(h3.x + e3v.x, 0.f) + EPSM;
                msg[13] = fmaxf(h3.y + e3v.y, 0.f) + EPSM;
                msg[14] = fmaxf(h3.z + e3v.z, 0.f) + EPSM;
                msg[15] = fmaxf(h3.w + e3v.w, 0.f) + EPSM;
                #pragma unroll
                for (int f = 0; f < 16; f++) {
                    float ev = __expf(t * msg[f]);
                    den[f] += ev;
                    num[f] += ev * msg[f];
                }
            }
        }
    }

    float pre[16];
    #pragma unroll
    for (int f = 0; f < 16; f++) {
        float dsum = wsum(den[f]);
        float nsum = wsum(num[f]);
        pre[f] = g_hp[(size_t)node * 16 + f] + nsum / fmaxf(dsum, 1e-16f);
    }

    // MLP: 16 -> 32 (LN, relu) -> 32 (then outer relu)
    float acc = sb2a[lane];
    #pragma unroll
    for (int f = 0; f < 16; f++) acc += pre[f] * sW2a[f * 32 + lane];
    float mu = wsum(acc) * (1.f / 32.f);
    float d = acc - mu;
    float var = wsum(d * d) * (1.f / 32.f);
    float y = d * rsqrtf(var + 1e-5f) * sg2[lane] + sbe2[lane];
    y = fmaxf(y, 0.f);
    sh_hid[w][lane] = y;
    __syncwarp();
    float o = sb2b[lane];
    #pragma unroll
    for (int k = 0; k < 32; k++) o += sh_hid[w][k] * sW2b[k * 32 + lane];
    g_h2[(size_t)node * 32 + lane] = fmaxf(o, 0.f);
}

// ---------------- pool + head: out = tanh(relu(pooled@Wa+ba)@Wo+bo) -------
__global__ void final_kernel(const float* __restrict__ Wa, const float* __restrict__ ba,
                             const float* __restrict__ Wo, const float* __restrict__ bo,
                             float* __restrict__ out) {
    __shared__ float part[128];
    __shared__ float pooled[32];
    __shared__ float sa[128];
    int t = threadIdx.x;
    int g = blockIdx.x;
    int c = t & 31, grp = t >> 5;
    float acc = 0.f;
    for (int n = grp; n < NPG; n += 4) {
        int node = g * NPG + n;
        if (g_mask[node] != 0.f) acc += g_h2[(size_t)node * 32 + c];
    }
    part[t] = acc;
    __syncthreads();
    if (t < 32) pooled[t] = (part[t] + part[t + 32] + part[t + 64] + part[t + 96]) * (1.f / KKEEP);
    __syncthreads();
    float a = ba[t];
    #pragma unroll
    for (int cc = 0; cc < 32; cc++) a += pooled[cc] * Wa[cc * 128 + t];
    sa[t] = fmaxf(a, 0.f);
    __syncthreads();
    if (t < 4) {
        float o = bo[t];
        for (int k = 0; k < 128; k++) o += sa[k] * Wo[k * 4 + t];
        out[g * 4 + t] = tanhf(o);
    }
}

// ---------------- launch ----------------
extern "C" void kernel_launch(void* const* d_in, const int* in_sizes, int n_in,
                              void* d_out, int out_size) {
    const float* x    = (const float*)d_in[0];
    const int*   ei   = (const int*)d_in[1];
    const float* ea   = (const float*)d_in[2];
    const float* Wne  = (const float*)d_in[3];
    const float* bne  = (const float*)d_in[4];
    const float* Wee  = (const float*)d_in[5];
    const float* bee  = (const float*)d_in[6];
    const float* t1   = (const float*)d_in[7];
    const float* W1a  = (const float*)d_in[8];
    const float* b1a  = (const float*)d_in[9];
    const float* g1   = (const float*)d_in[10];
    const float* be1  = (const float*)d_in[11];
    const float* W1b  = (const float*)d_in[12];
    const float* b1b  = (const float*)d_in[13];
    const float* wpl  = (const float*)d_in[14];
    const float* t2   = (const float*)d_in[15];
    const float* W2a  = (const float*)d_in[16];
    const float* b2a  = (const float*)d_in[17];
    const float* g2   = (const float*)d_in[18];
    const float* be2  = (const float*)d_in[19];
    const float* W2b  = (const float*)d_in[20];
    const float* b2b  = (const float*)d_in[21];
    const float* Wa   = (const float*)d_in[22];
    const float* ba   = (const float*)d_in[23];
    const float* Wo   = (const float*)d_in[24];
    const float* bo   = (const float*)d_in[25];
    float* out = (float*)d_out;

    build_csr_kernel<<<NGRAPH, 512>>>(ei);
    encode_edges_kernel<<<NE / 256, 256>>>(ea, Wee, bee);
    encode_kernel<<<BN / 256, 256>>>(x, Wne, bne);
    conv1_kernel<<<BN / 8, 256>>>(t1, W1a, b1a, g1, be1, W1b, b1b);
    topk_kernel<<<NGRAPH, NPG>>>(wpl);
    conv2_kernel<<<BN / 8, 256>>>(t2, W2a, b2a, g2, be2, W2b, b2b);
    final_kernel<<<NGRAPH, 128>>>(Wa, ba, Wo, bo, out);
}

// round 12
// speedup vs baseline: 2.4726x; 1.4335x over previous
#include <cuda_runtime.h>

#define BN      32768      // total nodes
#define NE      1048576    // total edges
#define NPG     512        // nodes per graph
#define EPG     16384      // edges per graph
#define KKEEP   256        // topk keep
#define NGRAPH  64
#define EPSM    1e-7f

// ---------------- scratch (device globals; no allocation allowed) ----------
__device__ float g_h   [BN * 16];
__device__ float g_h1  [BN * 16];
__device__ float g_hp  [BN * 16];
__device__ float g_h2  [BN * 32];
__device__ float g_mask[BN];
__device__ int   g_off[BN + 1];
__device__ int2  g_se  [NE];         // (src, eid) pairs, CSR(dst)-ordered
__device__ float g_ea  [NE * 16];    // encoded edge attr, ORIGINAL edge order

// ---------------- warp helpers ----------------
__device__ __forceinline__ float wsum(float v) {
    v += __shfl_xor_sync(0xffffffffu, v, 16);
    v += __shfl_xor_sync(0xffffffffu, v, 8);
    v += __shfl_xor_sync(0xffffffffu, v, 4);
    v += __shfl_xor_sync(0xffffffffu, v, 2);
    v += __shfl_xor_sync(0xffffffffu, v, 1);
    return v;
}
// reduce across the 8 edge-sublanes (xor 4, 8, 16), feature lanes stay separate
__device__ __forceinline__ float esum(float v) {
    v += __shfl_xor_sync(0xffffffffu, v, 4);
    v += __shfl_xor_sync(0xffffffffu, v, 8);
    v += __shfl_xor_sync(0xffffffffu, v, 16);
    return v;
}

// ---------------- edge encode (original order, fully coalesced) -----------
__global__ __launch_bounds__(256)
void encode_edges_kernel(const float* __restrict__ eattr,
                         const float* __restrict__ Wee,
                         const float* __restrict__ bee) {
    __shared__ float sW[256], sb[16];
    int tx = threadIdx.x;
    if (tx < 256) sW[tx] = Wee[tx];
    if (tx < 16) sb[tx] = bee[tx];
    __syncthreads();
    int e = blockIdx.x * blockDim.x + tx;
    if (e >= NE) return;

    float at[16];
    const float4* ap = (const float4*)(eattr) + (size_t)e * 4;
    float4 v;
    v = __ldg(ap + 0); at[0] = v.x; at[1] = v.y; at[2]  = v.z; at[3]  = v.w;
    v = __ldg(ap + 1); at[4] = v.x; at[5] = v.y; at[6]  = v.z; at[7]  = v.w;
    v = __ldg(ap + 2); at[8] = v.x; at[9] = v.y; at[10] = v.z; at[11] = v.w;
    v = __ldg(ap + 3); at[12] = v.x; at[13] = v.y; at[14] = v.z; at[15] = v.w;

    float enc[16];
    #pragma unroll
    for (int f = 0; f < 16; f++) {
        float acc = sb[f];
        #pragma unroll
        for (int j = 0; j < 16; j++) acc += at[j] * sW[j * 16 + f];
        enc[f] = acc;
    }
    float4* op = (float4*)(g_ea) + (size_t)e * 4;
    op[0] = make_float4(enc[0],  enc[1],  enc[2],  enc[3]);
    op[1] = make_float4(enc[4],  enc[5],  enc[6],  enc[7]);
    op[2] = make_float4(enc[8],  enc[9],  enc[10], enc[11]);
    op[3] = make_float4(enc[12], enc[13], enc[14], enc[15]);
}

// ---------------- CSR build: hist + scan + scatter, one block per graph ---
__global__ __launch_bounds__(512)
void build_csr_kernel(const int* __restrict__ ei) {
    __shared__ int sh[NPG];      // histogram, then cursor
    __shared__ int wsums[16];
    int g = blockIdx.x, tid = threadIdx.x, lane = tid & 31, w = tid >> 5;
    sh[tid] = 0;
    __syncthreads();
    int base = g * EPG;
    for (int it = 0; it < EPG / 512; it++) {
        int e = base + it * 512 + tid;
        int d = ei[NE + e] - g * NPG;
        if ((unsigned)d < NPG) atomicAdd(&sh[d], 1);
    }
    __syncthreads();
    // exclusive scan of sh[0..511]
    int v = sh[tid];
    int x = v;
    #pragma unroll
    for (int o = 1; o < 32; o <<= 1) {
        int y = __shfl_up_sync(0xffffffffu, x, o);
        if (lane >= o) x += y;
    }
    if (lane == 31) wsums[w] = x;
    __syncthreads();
    if (w == 0) {
        int s = (lane < 16) ? wsums[lane] : 0;
        #pragma unroll
        for (int o = 1; o < 16; o <<= 1) {
            int y = __shfl_up_sync(0xffffffffu, s, o);
            if (lane >= o) s += y;
        }
        if (lane < 16) wsums[lane] = s;
    }
    __syncthreads();
    int woff = (w == 0) ? 0 : wsums[w - 1];
    int incl = woff + x;
    int node = g * NPG + tid;
    g_off[node + 1] = base + incl;
    if (g == 0 && tid == 0) g_off[0] = 0;
    __syncthreads();
    sh[tid] = incl - v;          // local exclusive offset -> cursor
    __syncthreads();
    // scatter pass
    for (int it = 0; it < EPG / 512; it++) {
        int e = base + it * 512 + tid;
        int d = ei[NE + e] - g * NPG;
        int s = ei[e];
        if ((unsigned)s >= BN) s = 0;
        if ((unsigned)d < NPG) {
            int p = atomicAdd(&sh[d], 1);
            if ((unsigned)p < EPG) g_se[base + p] = make_int2(s, e);
        }
    }
}

// ---------------- node encode: h = x @ W_ne + b_ne ----------------
__global__ void encode_kernel(const float* __restrict__ x,
                              const float* __restrict__ Wne,
                              const float* __restrict__ bne) {
    __shared__ float sW[64 * 16];
    __shared__ float sb[16];
    int tx = threadIdx.x;
    for (int i = tx; i < 64 * 16; i += blockDim.x) sW[i] = Wne[i];
    if (tx < 16) sb[tx] = bne[tx];
    __syncthreads();
    int node = blockIdx.x * blockDim.x + tx;
    if (node >= BN) return;
    float acc[16];
    #pragma unroll
    for (int f = 0; f < 16; f++) acc[f] = sb[f];
    const float4* xp = (const float4*)(x + (size_t)node * 64);
    #pragma unroll
    for (int j4 = 0; j4 < 16; j4++) {
        float4 v = __ldg(xp + j4);
        float vv[4] = {v.x, v.y, v.z, v.w};
        #pragma unroll
        for (int k = 0; k < 4; k++) {
            int j = j4 * 4 + k;
            #pragma unroll
            for (int f = 0; f < 16; f++) acc[f] += vv[k] * sW[j * 16 + f];
        }
    }
    float4* op = (float4*)(g_h + (size_t)node * 16);
    op[0] = make_float4(acc[0], acc[1], acc[2], acc[3]);
    op[1] = make_float4(acc[4], acc[5], acc[6], acc[7]);
    op[2] = make_float4(acc[8], acc[9], acc[10], acc[11]);
    op[3] = make_float4(acc[12], acc[13], acc[14], acc[15]);
}

// ---------------- GENConv layer 1 (16 -> 32 -> 16) ----------------
// 4 lanes cooperate per edge: lane = 4*edge_sub + feature_group
__global__ __launch_bounds__(256)
void conv1_kernel(const float* __restrict__ tptr,
                  const float* __restrict__ W1a, const float* __restrict__ b1a,
                  const float* __restrict__ g1,  const float* __restrict__ be1,
                  const float* __restrict__ W1b, const float* __restrict__ b1b) {
    __shared__ float sW1a[512], sb1a[32], sg1[32], sbe1[32];
    __shared__ float sW1b[512], sb1b[16];
    __shared__ float sh_hid[8][33];
    __shared__ float sh_pre[8][16];
    int tx = threadIdx.x;
    for (int i = tx; i < 512; i += 256) { sW1a[i] = W1a[i]; sW1b[i] = W1b[i]; }
    if (tx < 32) { sb1a[tx] = b1a[tx]; sg1[tx] = g1[tx]; sbe1[tx] = be1[tx]; }
    if (tx < 16) { sb1b[tx] = b1b[tx]; }
    __syncthreads();

    int w = tx >> 5, lane = tx & 31;
    int esub = lane >> 2, fg = lane & 3;
    int node = blockIdx.x * 8 + w;
    int start = g_off[node], end = g_off[node + 1];
    if (start < 0) start = 0;
    if (end > NE) end = NE;
    float t = __ldg(tptr);

    float den0 = 0.f, den1 = 0.f, den2 = 0.f, den3 = 0.f;
    float num0 = 0.f, num1 = 0.f, num2 = 0.f, num3 = 0.f;

    for (int base = start; base < end; base += 8) {
        int idx = base + esub;
        if (idx < end) {
            int2 se = g_se[idx];
            float4 ev4 = ((const float4*)(g_ea))[(size_t)se.y * 4 + fg];
            float4 hv4 = ((const float4*)(g_h)) [(size_t)se.x * 4 + fg];
            float m0 = fmaxf(hv4.x + ev4.x, 0.f) + EPSM;
            float m1 = fmaxf(hv4.y + ev4.y, 0.f) + EPSM;
            float m2 = fmaxf(hv4.z + ev4.z, 0.f) + EPSM;
            float m3 = fmaxf(hv4.w + ev4.w, 0.f) + EPSM;
            float e0 = __expf(t * m0);
            float e1 = __expf(t * m1);
            float e2 = __expf(t * m2);
            float e3 = __expf(t * m3);
            den0 += e0; num0 += e0 * m0;
            den1 += e1; num1 += e1 * m1;
            den2 += e2; num2 += e2 * m2;
            den3 += e3; num3 += e3 * m3;
        }
    }

    den0 = esum(den0); num0 = esum(num0);
    den1 = esum(den1); num1 = esum(num1);
    den2 = esum(den2); num2 = esum(num2);
    den3 = esum(den3); num3 = esum(num3);

    if (esub == 0) {
        int fb = fg * 4;
        sh_pre[w][fb + 0] = g_h[(size_t)node * 16 + fb + 0] + num0 / fmaxf(den0, 1e-16f);
        sh_pre[w][fb + 1] = g_h[(size_t)node * 16 + fb + 1] + num1 / fmaxf(den1, 1e-16f);
        sh_pre[w][fb + 2] = g_h[(size_t)node * 16 + fb + 2] + num2 / fmaxf(den2, 1e-16f);
        sh_pre[w][fb + 3] = g_h[(size_t)node * 16 + fb + 3] + num3 / fmaxf(den3, 1e-16f);
    }
    __syncwarp();

    // MLP: 16 -> 32 (LN, relu) -> 16 (then outer relu)
    float acc = sb1a[lane];
    #pragma unroll
    for (int f = 0; f < 16; f++) acc += sh_pre[w][f] * sW1a[f * 32 + lane];
    float mu = wsum(acc) * (1.f / 32.f);
    float d = acc - mu;
    float var = wsum(d * d) * (1.f / 32.f);
    float y = d * rsqrtf(var + 1e-5f) * sg1[lane] + sbe1[lane];
    y = fmaxf(y, 0.f);
    sh_hid[w][lane] = y;
    __syncwarp();
    if (lane < 16) {
        float o = sb1b[lane];
        #pragma unroll
        for (int l = 0; l < 32; l++) o += sh_hid[w][l] * sW1b[l * 16 + lane];
        g_h1[(size_t)node * 16 + lane] = fmaxf(o, 0.f);
    }
}

// ---------------- TopK pooling (score + mask + hp) ----------------
__global__ void topk_kernel(const float* __restrict__ wpool) {
    __shared__ float s[512];
    __shared__ float swp[16];
    int tid = threadIdx.x;
    if (tid < 16) swp[tid] = wpool[tid];
    __syncthreads();
    float nrm2 = 0.f;
    #pragma unroll
    for (int j = 0; j < 16; j++) nrm2 += swp[j] * swp[j];
    float inv = rsqrtf(nrm2);
    int node = blockIdx.x * NPG + tid;
    const float4* hp4 = (const float4*)(g_h1) + (size_t)node * 4;
    float4 r0 = hp4[0], r1 = hp4[1], r2 = hp4[2], r3 = hp4[3];
    float dot = r0.x * swp[0] + r0.y * swp[1] + r0.z * swp[2] + r0.w * swp[3]
              + r1.x * swp[4] + r1.y * swp[5] + r1.z * swp[6] + r1.w * swp[7]
              + r2.x * swp[8] + r2.y * swp[9] + r2.z * swp[10] + r2.w * swp[11]
              + r3.x * swp[12] + r3.y * swp[13] + r3.z * swp[14] + r3.w * swp[15];
    float sc = dot * inv;
    s[tid] = sc;
    __syncthreads();
    int rank = 0;
    for (int j = 0; j < NPG; j++) {
        float sj = s[j];
        rank += (sj > sc) || (sj == sc && j < tid);
    }
    int kept = rank < KKEEP;
    g_mask[node] = kept ? 1.f : 0.f;
    float fac = kept ? tanhf(sc) : 0.f;
    float4* op = (float4*)(g_hp) + (size_t)node * 4;
    op[0] = make_float4(r0.x * fac, r0.y * fac, r0.z * fac, r0.w * fac);
    op[1] = make_float4(r1.x * fac, r1.y * fac, r1.z * fac, r1.w * fac);
    op[2] = make_float4(r2.x * fac, r2.y * fac, r2.z * fac, r2.w * fac);
    op[3] = make_float4(r3.x * fac, r3.y * fac, r3.z * fac, r3.w * fac);
}

// ---------------- GENConv layer 2 (16 -> 32 -> 32), kept nodes only -------
__global__ __launch_bounds__(256)
void conv2_kernel(const float* __restrict__ tptr,
                  const float* __restrict__ W2a, const float* __restrict__ b2a,
                  const float* __restrict__ g2,  const float* __restrict__ be2,
                  const float* __restrict__ W2b, const float* __restrict__ b2b) {
    __shared__ float sW2a[512], sb2a[32], sg2[32], sbe2[32];
    __shared__ float sW2b[1024], sb2b[32];
    __shared__ float sh_hid[8][33];
    __shared__ float sh_pre[8][16];
    int tx = threadIdx.x;
    for (int i = tx; i < 1024; i += 256) sW2b[i] = W2b[i];
    for (int i = tx; i < 512; i += 256) sW2a[i] = W2a[i];
    if (tx < 32) { sb2a[tx] = b2a[tx]; sg2[tx] = g2[tx]; sbe2[tx] = be2[tx]; sb2b[tx] = b2b[tx]; }
    __syncthreads();

    int w = tx >> 5, lane = tx & 31;
    int esub = lane >> 2, fg = lane & 3;
    int node = blockIdx.x * 8 + w;
    if (g_mask[node] == 0.f) return;   // not kept: h2 never read
    int start = g_off[node], end = g_off[node + 1];
    if (start < 0) start = 0;
    if (end > NE) end = NE;
    float t = __ldg(tptr);

    float den0 = 0.f, den1 = 0.f, den2 = 0.f, den3 = 0.f;
    float num0 = 0.f, num1 = 0.f, num2 = 0.f, num3 = 0.f;

    for (int base = start; base < end; base += 8) {
        int idx = base + esub;
        if (idx < end) {
            int2 se = g_se[idx];
            if (g_mask[se.x] != 0.f) {
                float4 ev4 = ((const float4*)(g_ea))[(size_t)se.y * 4 + fg];
                float4 hv4 = ((const float4*)(g_hp))[(size_t)se.x * 4 + fg];
                float m0 = fmaxf(hv4.x + ev4.x, 0.f) + EPSM;
                float m1 = fmaxf(hv4.y + ev4.y, 0.f) + EPSM;
                float m2 = fmaxf(hv4.z + ev4.z, 0.f) + EPSM;
                float m3 = fmaxf(hv4.w + ev4.w, 0.f) + EPSM;
                float e0 = __expf(t * m0);
                float e1 = __expf(t * m1);
                float e2 = __expf(t * m2);
                float e3 = __expf(t * m3);
                den0 += e0; num0 += e0 * m0;
                den1 += e1; num1 += e1 * m1;
                den2 += e2; num2 += e2 * m2;
                den3 += e3; num3 += e3 * m3;
            }
        }
    }

    den0 = esum(den0); num0 = esum(num0);
    den1 = esum(den1); num1 = esum(num1);
    den2 = esum(den2); num2 = esum(num2);
    den3 = esum(den3); num3 = esum(num3);

    if (esub == 0) {
        int fb = fg * 4;
        sh_pre[w][fb + 0] = g_hp[(size_t)node * 16 + fb + 0] + num0 / fmaxf(den0, 1e-16f);
        sh_pre[w][fb + 1] = g_hp[(size_t)node * 16 + fb + 1] + num1 / fmaxf(den1, 1e-16f);
        sh_pre[w][fb + 2] = g_hp[(size_t)node * 16 + fb + 2] + num2 / fmaxf(den2, 1e-16f);
        sh_pre[w][fb + 3] = g_hp[(size_t)node * 16 + fb + 3] + num3 / fmaxf(den3, 1e-16f);
    }
    __syncwarp();

    // MLP: 16 -> 32 (LN, relu) -> 32 (then outer relu)
    float acc = sb2a[lane];
    #pragma unroll
    for (int f = 0; f < 16; f++) acc += sh_pre[w][f] * sW2a[f * 32 + lane];
    float mu = wsum(acc) * (1.f / 32.f);
    float d = acc - mu;
    float var = wsum(d * d) * (1.f / 32.f);
    float y = d * rsqrtf(var + 1e-5f) * sg2[lane] + sbe2[lane];
    y = fmaxf(y, 0.f);
    sh_hid[w][lane] = y;
    __syncwarp();
    float o = sb2b[lane];
    #pragma unroll
    for (int k = 0; k < 32; k++) o += sh_hid[w][k] * sW2b[k * 32 + lane];
    g_h2[(size_t)node * 32 + lane] = fmaxf(o, 0.f);
}

// ---------------- pool + head: out = tanh(relu(pooled@Wa+ba)@Wo+bo) -------
__global__ void final_kernel(const float* __restrict__ Wa, const float* __restrict__ ba,
                             const float* __restrict__ Wo, const float* __restrict__ bo,
                             float* __restrict__ out) {
    __shared__ float part[128];
    __shared__ float pooled[32];
    __shared__ float sa[128];
    int t = threadIdx.x;
    int g = blockIdx.x;
    int c = t & 31, grp = t >> 5;
    float acc = 0.f;
    for (int n = grp; n < NPG; n += 4) {
        int node = g * NPG + n;
        if (g_mask[node] != 0.f) acc += g_h2[(size_t)node * 32 + c];
    }
    part[t] = acc;
    __syncthreads();
    if (t < 32) pooled[t] = (part[t] + part[t + 32] + part[t + 64] + part[t + 96]) * (1.f / KKEEP);
    __syncthreads();
    float a = ba[t];
    #pragma unroll
    for (int cc = 0; cc < 32; cc++) a += pooled[cc] * Wa[cc * 128 + t];
    sa[t] = fmaxf(a, 0.f);
    __syncthreads();
    if (t < 4) {
        float o = bo[t];
        for (int k = 0; k < 128; k++) o += sa[k] * Wo[k * 4 + t];
        out[g * 4 + t] = tanhf(o);
    }
}

// ---------------- launch ----------------
extern "C" void kernel_launch(void* const* d_in, const int* in_sizes, int n_in,
                              void* d_out, int out_size) {
    const float* x    = (const float*)d_in[0];
    const int*   ei   = (const int*)d_in[1];
    const float* ea   = (const float*)d_in[2];
    const float* Wne  = (const float*)d_in[3];
    const float* bne  = (const float*)d_in[4];
    const float* Wee  = (const float*)d_in[5];
    const float* bee  = (const float*)d_in[6];
    const float* t1   = (const float*)d_in[7];
    const float* W1a  = (const float*)d_in[8];
    const float* b1a  = (const float*)d_in[9];
    const float* g1   = (const float*)d_in[10];
    const float* be1  = (const float*)d_in[11];
    const float* W1b  = (const float*)d_in[12];
    const float* b1b  = (const float*)d_in[13];
    const float* wpl  = (const float*)d_in[14];
    const float* t2   = (const float*)d_in[15];
    const float* W2a  = (const float*)d_in[16];
    const float* b2a  = (const float*)d_in[17];
    const float* g2   = (const float*)d_in[18];
    const float* be2  = (const float*)d_in[19];
    const float* W2b  = (const float*)d_in[20];
    const float* b2b  = (const float*)d_in[21];
    const float* Wa   = (const float*)d_in[22];
    const float* ba   = (const float*)d_in[23];
    const float* Wo   = (const float*)d_in[24];
    const float* bo   = (const float*)d_in[25];
    float* out = (float*)d_out;

    build_csr_kernel<<<NGRAPH, 512>>>(ei);
    encode_edges_kernel<<<NE / 256, 256>>>(ea, Wee, bee);
    encode_kernel<<<BN / 256, 256>>>(x, Wne, bne);
    conv1_kernel<<<BN / 8, 256>>>(t1, W1a, b1a, g1, be1, W1b, b1b);
    topk_kernel<<<NGRAPH, NPG>>>(wpl);
    conv2_kernel<<<BN / 8, 256>>>(t2, W2a, b2a, g2, be2, W2b, b2b);
    final_kernel<<<NGRAPH, 128>>>(Wa, ba, Wo, bo, out);
}

// round 14
// speedup vs baseline: 2.5337x; 1.0247x over previous
#include <cuda_runtime.h>
#include <cuda_fp16.h>

#define BN      32768      // total nodes
#define NE      1048576    // total edges
#define NPG     512        // nodes per graph
#define EPG     16384      // edges per graph
#define KKEEP   256        // topk keep
#define NGRAPH  64
#define EPSM    1e-7f

// ---------------- scratch (device globals; no allocation allowed) ----------
__device__ float  g_h   [BN * 16];
__device__ float  g_h1  [BN * 16];
__device__ float  g_hp  [BN * 16];
__device__ float  g_h2  [BN * 32];
__device__ float  g_mask[BN];
__device__ int    g_off[BN + 1];
__device__ int2   g_se  [NE];        // (src, eid) pairs, CSR(dst)-ordered
__device__ __half g_ea  [NE * 16];   // encoded edge attr (fp16), ORIGINAL edge order

// ---------------- warp helpers ----------------
__device__ __forceinline__ float wsum(float v) {
    v += __shfl_xor_sync(0xffffffffu, v, 16);
    v += __shfl_xor_sync(0xffffffffu, v, 8);
    v += __shfl_xor_sync(0xffffffffu, v, 4);
    v += __shfl_xor_sync(0xffffffffu, v, 2);
    v += __shfl_xor_sync(0xffffffffu, v, 1);
    return v;
}
// reduce across the 16 edge-sublanes (xor 2,4,8,16); feature lanes (bit 0) stay separate
__device__ __forceinline__ float esum16(float v) {
    v += __shfl_xor_sync(0xffffffffu, v, 2);
    v += __shfl_xor_sync(0xffffffffu, v, 4);
    v += __shfl_xor_sync(0xffffffffu, v, 8);
    v += __shfl_xor_sync(0xffffffffu, v, 16);
    return v;
}

__device__ __forceinline__ unsigned int pack_h2(float a, float b) {
    __half2 h = __floats2half2_rn(a, b);
    return *reinterpret_cast<unsigned int*>(&h);
}
__device__ __forceinline__ float2 unpack_h2(unsigned int u) {
    __half2 h = *reinterpret_cast<__half2*>(&u);
    return __half22float2(h);
}

// ---------------- edge encode (original order, fully coalesced, fp16 out) --
__global__ __launch_bounds__(256)
void encode_edges_kernel(const float* __restrict__ eattr,
                         const float* __restrict__ Wee,
                         const float* __restrict__ bee) {
    __shared__ float sW[256], sb[16];
    int tx = threadIdx.x;
    if (tx < 256) sW[tx] = Wee[tx];
    if (tx < 16) sb[tx] = bee[tx];
    __syncthreads();
    int e = blockIdx.x * blockDim.x + tx;
    if (e >= NE) return;

    float at[16];
    const float4* ap = (const float4*)(eattr) + (size_t)e * 4;
    float4 v;
    v = __ldg(ap + 0); at[0] = v.x; at[1] = v.y; at[2]  = v.z; at[3]  = v.w;
    v = __ldg(ap + 1); at[4] = v.x; at[5] = v.y; at[6]  = v.z; at[7]  = v.w;
    v = __ldg(ap + 2); at[8] = v.x; at[9] = v.y; at[10] = v.z; at[11] = v.w;
    v = __ldg(ap + 3); at[12] = v.x; at[13] = v.y; at[14] = v.z; at[15] = v.w;

    float enc[16];
    #pragma unroll
    for (int f = 0; f < 16; f++) {
        float acc = sb[f];
        #pragma unroll
        for (int j = 0; j < 16; j++) acc += at[j] * sW[j * 16 + f];
        enc[f] = acc;
    }
    uint4 lo, hi;
    lo.x = pack_h2(enc[0],  enc[1]);  lo.y = pack_h2(enc[2],  enc[3]);
    lo.z = pack_h2(enc[4],  enc[5]);  lo.w = pack_h2(enc[6],  enc[7]);
    hi.x = pack_h2(enc[8],  enc[9]);  hi.y = pack_h2(enc[10], enc[11]);
    hi.z = pack_h2(enc[12], enc[13]); hi.w = pack_h2(enc[14], enc[15]);
    uint4* op = (uint4*)(g_ea) + (size_t)e * 2;
    op[0] = lo;
    op[1] = hi;
}

// ---------------- CSR build: hist + scan + scatter, one block per graph ---
__global__ __launch_bounds__(512)
void build_csr_kernel(const int* __restrict__ ei) {
    __shared__ int sh[NPG];      // histogram, then cursor
    __shared__ int wsums[16];
    int g = blockIdx.x, tid = threadIdx.x, lane = tid & 31, w = tid >> 5;
    sh[tid] = 0;
    __syncthreads();
    int base = g * EPG;
    for (int it = 0; it < EPG / 512; it++) {
        int e = base + it * 512 + tid;
        int d = ei[NE + e] - g * NPG;
        if ((unsigned)d < NPG) atomicAdd(&sh[d], 1);
    }
    __syncthreads();
    // exclusive scan of sh[0..511]
    int v = sh[tid];
    int x = v;
    #pragma unroll
    for (int o = 1; o < 32; o <<= 1) {
        int y = __shfl_up_sync(0xffffffffu, x, o);
        if (lane >= o) x += y;
    }
    if (lane == 31) wsums[w] = x;
    __syncthreads();
    if (w == 0) {
        int s = (lane < 16) ? wsums[lane] : 0;
        #pragma unroll
        for (int o = 1; o < 16; o <<= 1) {
            int y = __shfl_up_sync(0xffffffffu, s, o);
            if (lane >= o) s += y;
        }
        if (lane < 16) wsums[lane] = s;
    }
    __syncthreads();
    int woff = (w == 0) ? 0 : wsums[w - 1];
    int incl = woff + x;
    int node = g * NPG + tid;
    g_off[node + 1] = base + incl;
    if (g == 0 && tid == 0) g_off[0] = 0;
    __syncthreads();
    sh[tid] = incl - v;          // local exclusive offset -> cursor
    __syncthreads();
    // scatter pass
    for (int it = 0; it < EPG / 512; it++) {
        int e = base + it * 512 + tid;
        int d = ei[NE + e] - g * NPG;
        int s = ei[e];
        if ((unsigned)s >= BN) s = 0;
        if ((unsigned)d < NPG) {
            int p = atomicAdd(&sh[d], 1);
            if ((unsigned)p < EPG) g_se[base + p] = make_int2(s, e);
        }
    }
}

// ---------------- node encode: h = x @ W_ne + b_ne ----------------
__global__ void encode_kernel(const float* __restrict__ x,
                              const float* __restrict__ Wne,
                              const float* __restrict__ bne) {
    __shared__ float sW[64 * 16];
    __shared__ float sb[16];
    int tx = threadIdx.x;
    for (int i = tx; i < 64 * 16; i += blockDim.x) sW[i] = Wne[i];
    if (tx < 16) sb[tx] = bne[tx];
    __syncthreads();
    int node = blockIdx.x * blockDim.x + tx;
    if (node >= BN) return;
    float acc[16];
    #pragma unroll
    for (int f = 0; f < 16; f++) acc[f] = sb[f];
    const float4* xp = (const float4*)(x + (size_t)node * 64);
    #pragma unroll
    for (int j4 = 0; j4 < 16; j4++) {
        float4 v = __ldg(xp + j4);
        float vv[4] = {v.x, v.y, v.z, v.w};
        #pragma unroll
        for (int k = 0; k < 4; k++) {
            int j = j4 * 4 + k;
            #pragma unroll
            for (int f = 0; f < 16; f++) acc[f] += vv[k] * sW[j * 16 + f];
        }
    }
    float4* op = (float4*)(g_h + (size_t)node * 16);
    op[0] = make_float4(acc[0], acc[1], acc[2], acc[3]);
    op[1] = make_float4(acc[4], acc[5], acc[6], acc[7]);
    op[2] = make_float4(acc[8], acc[9], acc[10], acc[11]);
    op[3] = make_float4(acc[12], acc[13], acc[14], acc[15]);
}

// ---------------- GENConv layer 1 (16 -> 32 -> 16) ----------------
// 2 lanes cooperate per edge: lane = 2*edge_sub + feature_half (8 features each)
__global__ __launch_bounds__(256)
void conv1_kernel(const float* __restrict__ tptr,
                  const float* __restrict__ W1a, const float* __restrict__ b1a,
                  const float* __restrict__ g1,  const float* __restrict__ be1,
                  const float* __restrict__ W1b, const float* __restrict__ b1b) {
    __shared__ float sW1a[512], sb1a[32], sg1[32], sbe1[32];
    __shared__ float sW1b[512], sb1b[16];
    __shared__ float sh_hid[8][33];
    __shared__ float sh_pre[8][16];
    int tx = threadIdx.x;
    for (int i = tx; i < 512; i += 256) { sW1a[i] = W1a[i]; sW1b[i] = W1b[i]; }
    if (tx < 32) { sb1a[tx] = b1a[tx]; sg1[tx] = g1[tx]; sbe1[tx] = be1[tx]; }
    if (tx < 16) { sb1b[tx] = b1b[tx]; }
    __syncthreads();

    int w = tx >> 5, lane = tx & 31;
    int esub = lane >> 1, fg = lane & 1;
    int node = blockIdx.x * 8 + w;
    int start = g_off[node], end = g_off[node + 1];
    if (start < 0) start = 0;
    if (end > NE) end = NE;
    float t = __ldg(tptr);

    float d0 = 0.f, d1 = 0.f, d2 = 0.f, d3 = 0.f, d4 = 0.f, d5 = 0.f, d6 = 0.f, d7 = 0.f;
    float n0 = 0.f, n1 = 0.f, n2 = 0.f, n3 = 0.f, n4 = 0.f, n5 = 0.f, n6 = 0.f, n7 = 0.f;

    for (int base = start; base < end; base += 16) {
        int idx = base + esub;
        if (idx < end) {
            int2 se = g_se[idx];
            uint4 ev = ((const uint4*)(g_ea))[(size_t)se.y * 2 + fg];
            const float4* hp4 = (const float4*)(g_h) + (size_t)se.x * 4 + fg * 2;
            float4 ha = hp4[0], hb = hp4[1];
            float2 p0 = unpack_h2(ev.x), p1 = unpack_h2(ev.y);
            float2 p2 = unpack_h2(ev.z), p3 = unpack_h2(ev.w);
            float m0 = fmaxf(ha.x + p0.x, 0.f) + EPSM;
            float m1 = fmaxf(ha.y + p0.y, 0.f) + EPSM;
            float m2 = fmaxf(ha.z + p1.x, 0.f) + EPSM;
            float m3 = fmaxf(ha.w + p1.y, 0.f) + EPSM;
            float m4 = fmaxf(hb.x + p2.x, 0.f) + EPSM;
            float m5 = fmaxf(hb.y + p2.y, 0.f) + EPSM;
            float m6 = fmaxf(hb.z + p3.x, 0.f) + EPSM;
            float m7 = fmaxf(hb.w + p3.y, 0.f) + EPSM;
            float e0 = __expf(t * m0), e1 = __expf(t * m1);
            float e2 = __expf(t * m2), e3 = __expf(t * m3);
            float e4 = __expf(t * m4), e5 = __expf(t * m5);
            float e6 = __expf(t * m6), e7 = __expf(t * m7);
            d0 += e0; n0 += e0 * m0;
            d1 += e1; n1 += e1 * m1;
            d2 += e2; n2 += e2 * m2;
            d3 += e3; n3 += e3 * m3;
            d4 += e4; n4 += e4 * m4;
            d5 += e5; n5 += e5 * m5;
            d6 += e6; n6 += e6 * m6;
            d7 += e7; n7 += e7 * m7;
        }
    }

    d0 = esum16(d0); n0 = esum16(n0);
    d1 = esum16(d1); n1 = esum16(n1);
    d2 = esum16(d2); n2 = esum16(n2);
    d3 = esum16(d3); n3 = esum16(n3);
    d4 = esum16(d4); n4 = esum16(n4);
    d5 = esum16(d5); n5 = esum16(n5);
    d6 = esum16(d6); n6 = esum16(n6);
    d7 = esum16(d7); n7 = esum16(n7);

    if (esub == 0) {
        int fb = fg * 8;
        const float* hb = g_h + (size_t)node * 16 + fb;
        sh_pre[w][fb + 0] = hb[0] + n0 / fmaxf(d0, 1e-16f);
        sh_pre[w][fb + 1] = hb[1] + n1 / fmaxf(d1, 1e-16f);
        sh_pre[w][fb + 2] = hb[2] + n2 / fmaxf(d2, 1e-16f);
        sh_pre[w][fb + 3] = hb[3] + n3 / fmaxf(d3, 1e-16f);
        sh_pre[w][fb + 4] = hb[4] + n4 / fmaxf(d4, 1e-16f);
        sh_pre[w][fb + 5] = hb[5] + n5 / fmaxf(d5, 1e-16f);
        sh_pre[w][fb + 6] = hb[6] + n6 / fmaxf(d6, 1e-16f);
        sh_pre[w][fb + 7] = hb[7] + n7 / fmaxf(d7, 1e-16f);
    }
    __syncwarp();

    // MLP: 16 -> 32 (LN, relu) -> 16 (then outer relu)
    float acc = sb1a[lane];
    #pragma unroll
    for (int f = 0; f < 16; f++) acc += sh_pre[w][f] * sW1a[f * 32 + lane];
    float mu = wsum(acc) * (1.f / 32.f);
    float d = acc - mu;
    float var = wsum(d * d) * (1.f / 32.f);
    float y = d * rsqrtf(var + 1e-5f) * sg1[lane] + sbe1[lane];
    y = fmaxf(y, 0.f);
    sh_hid[w][lane] = y;
    __syncwarp();
    if (lane < 16) {
        float o = sb1b[lane];
        #pragma unroll
        for (int l = 0; l < 32; l++) o += sh_hid[w][l] * sW1b[l * 16 + lane];
        g_h1[(size_t)node * 16 + lane] = fmaxf(o, 0.f);
    }
}

// ---------------- TopK pooling (score + mask + hp) ----------------
__global__ void topk_kernel(const float* __restrict__ wpool) {
    __shared__ float4 s4[NPG / 4];
    __shared__ float swp[16];
    int tid = threadIdx.x;
    if (tid < 16) swp[tid] = wpool[tid];
    __syncthreads();
    float nrm2 = 0.f;
    #pragma unroll
    for (int j = 0; j < 16; j++) nrm2 += swp[j] * swp[j];
    float inv = rsqrtf(nrm2);
    int node = blockIdx.x * NPG + tid;
    const float4* hp4 = (const float4*)(g_h1) + (size_t)node * 4;
    float4 r0 = hp4[0], r1 = hp4[1], r2 = hp4[2], r3 = hp4[3];
    float dot = r0.x * swp[0] + r0.y * swp[1] + r0.z * swp[2] + r0.w * swp[3]
              + r1.x * swp[4] + r1.y * swp[5] + r1.z * swp[6] + r1.w * swp[7]
              + r2.x * swp[8] + r2.y * swp[9] + r2.z * swp[10] + r2.w * swp[11]
              + r3.x * swp[12] + r3.y * swp[13] + r3.z * swp[14] + r3.w * swp[15];
    float sc = dot * inv;
    ((float*)s4)[tid] = sc;
    __syncthreads();
    int rank = 0;
    #pragma unroll 4
    for (int j4 = 0; j4 < NPG / 4; j4++) {
        float4 v = s4[j4];
        int j = j4 * 4;
        rank += (v.x > sc) || (v.x == sc && (j + 0) < tid);
        rank += (v.y > sc) || (v.y == sc && (j + 1) < tid);
        rank += (v.z > sc) || (v.z == sc && (j + 2) < tid);
        rank += (v.w > sc) || (v.w == sc && (j + 3) < tid);
    }
    int kept = rank < KKEEP;
    g_mask[node] = kept ? 1.f : 0.f;
    float fac = kept ? tanhf(sc) : 0.f;
    float4* op = (float4*)(g_hp) + (size_t)node * 4;
    op[0] = make_float4(r0.x * fac, r0.y * fac, r0.z * fac, r0.w * fac);
    op[1] = make_float4(r1.x * fac, r1.y * fac, r1.z * fac, r1.w * fac);
    op[2] = make_float4(r2.x * fac, r2.y * fac, r2.z * fac, r2.w * fac);
    op[3] = make_float4(r3.x * fac, r3.y * fac, r3.z * fac, r3.w * fac);
}

// ---------------- GENConv layer 2 (16 -> 32 -> 32), kept nodes only -------
__global__ __launch_bounds__(256)
void conv2_kernel(const float* __restrict__ tptr,
                  const float* __restrict__ W2a, const float* __restrict__ b2a,
                  const float* __restrict__ g2,  const float* __restrict__ be2,
                  const float* __restrict__ W2b, const float* __restrict__ b2b) {
    __shared__ float sW2a[512], sb2a[32], sg2[32], sbe2[32];
    __shared__ float sW2b[1024], sb2b[32];
    __shared__ float sh_hid[8][33];
    __shared__ float sh_pre[8][16];
    int tx = threadIdx.x;
    for (int i = tx; i < 1024; i += 256) sW2b[i] = W2b[i];
    for (int i = tx; i < 512; i += 256) sW2a[i] = W2a[i];
    if (tx < 32) { sb2a[tx] = b2a[tx]; sg2[tx] = g2[tx]; sbe2[tx] = be2[tx]; sb2b[tx] = b2b[tx]; }
    __syncthreads();

    int w = tx >> 5, lane = tx & 31;
    int esub = lane >> 1, fg = lane & 1;
    int node = blockIdx.x * 8 + w;
    if (g_mask[node] == 0.f) return;   // not kept: h2 never read
    int start = g_off[node], end = g_off[node + 1];
    if (start < 0) start = 0;
    if (end > NE) end = NE;
    float t = __ldg(tptr);

    float d0 = 0.f, d1 = 0.f, d2 = 0.f, d3 = 0.f, d4 = 0.f, d5 = 0.f, d6 = 0.f, d7 = 0.f;
    float n0 = 0.f, n1 = 0.f, n2 = 0.f, n3 = 0.f, n4 = 0.f, n5 = 0.f, n6 = 0.f, n7 = 0.f;

    for (int base = start; base < end; base += 16) {
        int idx = base + esub;
        if (idx < end) {
            int2 se = g_se[idx];
            if (g_mask[se.x] != 0.f) {
                uint4 ev = ((const uint4*)(g_ea))[(size_t)se.y * 2 + fg];
                const float4* hp4 = (const float4*)(g_hp) + (size_t)se.x * 4 + fg * 2;
                float4 ha = hp4[0], hb = hp4[1];
                float2 p0 = unpack_h2(ev.x), p1 = unpack_h2(ev.y);
                float2 p2 = unpack_h2(ev.z), p3 = unpack_h2(ev.w);
                float m0 = fmaxf(ha.x + p0.x, 0.f) + EPSM;
                float m1 = fmaxf(ha.y + p0.y, 0.f) + EPSM;
                float m2 = fmaxf(ha.z + p1.x, 0.f) + EPSM;
                float m3 = fmaxf(ha.w + p1.y, 0.f) + EPSM;
                float m4 = fmaxf(hb.x + p2.x, 0.f) + EPSM;
                float m5 = fmaxf(hb.y + p2.y, 0.f) + EPSM;
                float m6 = fmaxf(hb.z + p3.x, 0.f) + EPSM;
                float m7 = fmaxf(hb.w + p3.y, 0.f) + EPSM;
                float e0 = __expf(t * m0), e1 = __expf(t * m1);
                float e2 = __expf(t * m2), e3 = __expf(t * m3);
                float e4 = __expf(t * m4), e5 = __expf(t * m5);
                float e6 = __expf(t * m6), e7 = __expf(t * m7);
                d0 += e0; n0 += e0 * m0;
                d1 += e1; n1 += e1 * m1;
                d2 += e2; n2 += e2 * m2;
                d3 += e3; n3 += e3 * m3;
                d4 += e4; n4 += e4 * m4;
                d5 += e5; n5 += e5 * m5;
                d6 += e6; n6 += e6 * m6;
                d7 += e7; n7 += e7 * m7;
            }
        }
    }

    d0 = esum16(d0); n0 = esum16(n0);
    d1 = esum16(d1); n1 = esum16(n1);
    d2 = esum16(d2); n2 = esum16(n2);
    d3 = esum16(d3); n3 = esum16(n3);
    d4 = esum16(d4); n4 = esum16(n4);
    d5 = esum16(d5); n5 = esum16(n5);
    d6 = esum16(d6); n6 = esum16(n6);
    d7 = esum16(d7); n7 = esum16(n7);

    if (esub == 0) {
        int fb = fg * 8;
        const float* hb = g_hp + (size_t)node * 16 + fb;
        sh_pre[w][fb + 0] = hb[0] + n0 / fmaxf(d0, 1e-16f);
        sh_pre[w][fb + 1] = hb[1] + n1 / fmaxf(d1, 1e-16f);
        sh_pre[w][fb + 2] = hb[2] + n2 / fmaxf(d2, 1e-16f);
        sh_pre[w][fb + 3] = hb[3] + n3 / fmaxf(d3, 1e-16f);
        sh_pre[w][fb + 4] = hb[4] + n4 / fmaxf(d4, 1e-16f);
        sh_pre[w][fb + 5] = hb[5] + n5 / fmaxf(d5, 1e-16f);
        sh_pre[w][fb + 6] = hb[6] + n6 / fmaxf(d6, 1e-16f);
        sh_pre[w][fb + 7] = hb[7] + n7 / fmaxf(d7, 1e-16f);
    }
    __syncwarp();

    // MLP: 16 -> 32 (LN, relu) -> 32 (then outer relu)
    float acc = sb2a[lane];
    #pragma unroll
    for (int f = 0; f < 16; f++) acc += sh_pre[w][f] * sW2a[f * 32 + lane];
    float mu = wsum(acc) * (1.f / 32.f);
    float d = acc - mu;
    float var = wsum(d * d) * (1.f / 32.f);
    float y = d * rsqrtf(var + 1e-5f) * sg2[lane] + sbe2[lane];
    y = fmaxf(y, 0.f);
    sh_hid[w][lane] = y;
    __syncwarp();
    float o = sb2b[lane];
    #pragma unroll
    for (int k = 0; k < 32; k++) o += sh_hid[w][k] * sW2b[k * 32 + lane];
    g_h2[(size_t)node * 32 + lane] = fmaxf(o, 0.f);
}

// ---------------- pool + head: out = tanh(relu(pooled@Wa+ba)@Wo+bo) -------
__global__ void final_kernel(const float* __restrict__ Wa, const float* __restrict__ ba,
                             const float* __restrict__ Wo, const float* __restrict__ bo,
                             float* __restrict__ out) {
    __shared__ float part[128];
    __shared__ float pooled[32];
    __shared__ float sa[128];
    int t = threadIdx.x;
    int g = blockIdx.x;
    int c = t & 31, grp = t >> 5;
    float acc = 0.f;
    for (int n = grp; n < NPG; n += 4) {
        int node = g * NPG + n;
        if (g_mask[node] != 0.f) acc += g_h2[(size_t)node * 32 + c];
    }
    part[t] = acc;
    __syncthreads();
    if (t < 32) pooled[t] = (part[t] + part[t + 32] + part[t + 64] + part[t + 96]) * (1.f / KKEEP);
    __syncthreads();
    float a = ba[t];
    #pragma unroll
    for (int cc = 0; cc < 32; cc++) a += pooled[cc] * Wa[cc * 128 + t];
    sa[t] = fmaxf(a, 0.f);
    __syncthreads();
    if (t < 4) {
        float o = bo[t];
        for (int k = 0; k < 128; k++) o += sa[k] * Wo[k * 4 + t];
        out[g * 4 + t] = tanhf(o);
    }
}

// ---------------- launch ----------------
extern "C" void kernel_launch(void* const* d_in, const int* in_sizes, int n_in,
                              void* d_out, int out_size) {
    const float* x    = (const float*)d_in[0];
    const int*   ei   = (const int*)d_in[1];
    const float* ea   = (const float*)d_in[2];
    const float* Wne  = (const float*)d_in[3];
    const float* bne  = (const float*)d_in[4];
    const float* Wee  = (const float*)d_in[5];
    const float* bee  = (const float*)d_in[6];
    const float* t1   = (const float*)d_in[7];
    const float* W1a  = (const float*)d_in[8];
    const float* b1a  = (const float*)d_in[9];
    const float* g1   = (const float*)d_in[10];
    const float* be1  = (const float*)d_in[11];
    const float* W1b  = (const float*)d_in[12];
    const float* b1b  = (const float*)d_in[13];
    const float* wpl  = (const float*)d_in[14];
    const float* t2   = (const float*)d_in[15];
    const float* W2a  = (const float*)d_in[16];
    const float* b2a  = (const float*)d_in[17];
    const float* g2   = (const float*)d_in[18];
    const float* be2  = (const float*)d_in[19];
    const float* W2b  = (const float*)d_in[20];
    const float* b2b  = (const float*)d_in[21];
    const float* Wa   = (const float*)d_in[22];
    const float* ba   = (const float*)d_in[23];
    const float* Wo   = (const float*)d_in[24];
    const float* bo   = (const float*)d_in[25];
    float* out = (float*)d_out;

    build_csr_kernel<<<NGRAPH, 512>>>(ei);
    encode_edges_kernel<<<NE / 256, 256>>>(ea, Wee, bee);
    encode_kernel<<<BN / 256, 256>>>(x, Wne, bne);
    conv1_kernel<<<BN / 8, 256>>>(t1, W1a, b1a, g1, be1, W1b, b1b);
    topk_kernel<<<NGRAPH, NPG>>>(wpl);
    conv2_kernel<<<BN / 8, 256>>>(t2, W2a, b2a, g2, be2, W2b, b2b);
    final_kernel<<<NGRAPH, 128>>>(Wa, ba, Wo, bo, out);
}